// round 1
// baseline (speedup 1.0000x reference)
#include <cuda_runtime.h>
#include <cuda_fp16.h>

// Sinkhorn (eps=0.1, 50 iters) on N=8, P1=P2=2048.
// Exp-domain matrix scaling with fp16 K = exp(-C/eps), fully L2-resident (67 MB).
//   a = (mu+1e-8)/(K b);  b = (nu+1e-8)/(K^T a)
// Final pi computed from exact f32 C: pi = a_i * b_j * exp(-C/eps).

#define NB 8
#define PP 2048
#define M_ELEMS (NB * (size_t)PP * (size_t)PP)   // 33,554,432
#define INV_EPS 10.0f
#define NITER 50
#define LOGEPS 1e-8f

__device__ __half g_K[M_ELEMS];          // 64 MiB scratch
__device__ float  g_a[NB * PP];
__device__ float  g_b[NB * PP];
__device__ float  g_part[4096];

// ---------------------------------------------------------------------------
// Prologue: K = fp16(exp(-C/eps)); init b = 1 (v0 = 0).
// grid 16384 x 256, 8 elems/thread.
// ---------------------------------------------------------------------------
__global__ void __launch_bounds__(256) prologue_kernel(const float* __restrict__ C) {
    size_t tid  = (size_t)blockIdx.x * 256 + threadIdx.x;
    size_t base = tid * 8;
    float4 c0 = *(const float4*)(C + base);
    float4 c1 = *(const float4*)(C + base + 4);
    union { __half2 h2[4]; uint4 u; } pk;
    pk.h2[0] = __floats2half2_rn(__expf(-INV_EPS * c0.x), __expf(-INV_EPS * c0.y));
    pk.h2[1] = __floats2half2_rn(__expf(-INV_EPS * c0.z), __expf(-INV_EPS * c0.w));
    pk.h2[2] = __floats2half2_rn(__expf(-INV_EPS * c1.x), __expf(-INV_EPS * c1.y));
    pk.h2[3] = __floats2half2_rn(__expf(-INV_EPS * c1.z), __expf(-INV_EPS * c1.w));
    *(uint4*)(g_K + base) = pk.u;
    if (tid < (size_t)NB * PP) g_b[tid] = 1.0f;
}

// ---------------------------------------------------------------------------
// Row pass: s_i = sum_j K_ij * b_j;  a_i = (mu_i + 1e-8) / s_i.
// 128 threads (4 warps), 16 rows/warp, 64 rows/CTA. grid = 8*32 = 256.
// Each lane holds its 64 b-values in registers (lane l owns j = it*256 + l*8 + {0..7}).
// ---------------------------------------------------------------------------
__global__ void __launch_bounds__(128) rowpass_kernel(const float* __restrict__ mu) {
    int batch = blockIdx.x >> 5;
    int blk   = blockIdx.x & 31;
    int w = threadIdx.x >> 5;
    int l = threadIdx.x & 31;
    int row0 = blk * 64 + w * 16;

    const float* bptr = g_b + batch * PP;
    float bb[8][8];
#pragma unroll
    for (int it = 0; it < 8; it++) {
        float4 b0 = *(const float4*)(bptr + it * 256 + l * 8);
        float4 b1 = *(const float4*)(bptr + it * 256 + l * 8 + 4);
        bb[it][0] = b0.x; bb[it][1] = b0.y; bb[it][2] = b0.z; bb[it][3] = b0.w;
        bb[it][4] = b1.x; bb[it][5] = b1.y; bb[it][6] = b1.z; bb[it][7] = b1.w;
    }

#pragma unroll 1
    for (int r = 0; r < 16; r++) {
        int row = batch * PP + row0 + r;
        const __half* Krow = g_K + (size_t)row * PP;
        float s0 = 0.f, s1 = 0.f, s2 = 0.f, s3 = 0.f;
#pragma unroll
        for (int it = 0; it < 8; it++) {
            uint4 kv = *(const uint4*)(Krow + it * 256 + l * 8);
            const __half2* h2 = (const __half2*)&kv;
            float2 f0 = __half22float2(h2[0]);
            float2 f1 = __half22float2(h2[1]);
            float2 f2 = __half22float2(h2[2]);
            float2 f3 = __half22float2(h2[3]);
            s0 = fmaf(f0.x, bb[it][0], s0);
            s1 = fmaf(f0.y, bb[it][1], s1);
            s2 = fmaf(f1.x, bb[it][2], s2);
            s3 = fmaf(f1.y, bb[it][3], s3);
            s0 = fmaf(f2.x, bb[it][4], s0);
            s1 = fmaf(f2.y, bb[it][5], s1);
            s2 = fmaf(f3.x, bb[it][6], s2);
            s3 = fmaf(f3.y, bb[it][7], s3);
        }
        float s = (s0 + s1) + (s2 + s3);
#pragma unroll
        for (int off = 16; off; off >>= 1) s += __shfl_xor_sync(0xffffffffu, s, off);
        if (l == 0) g_a[row] = (mu[row] + LOGEPS) / s;
    }
}

// ---------------------------------------------------------------------------
// Col pass: t_j = sum_i K_ij * a_i;  b_j = (nu_j + 1e-8) / t_j.
// 256 threads, CTA owns 16 columns; thread t handles rows t + 256q.
// grid = 8*128 = 1024. No atomics; deterministic tree reduction.
// ---------------------------------------------------------------------------
__global__ void __launch_bounds__(256) colpass_kernel(const float* __restrict__ nu) {
    int batch = blockIdx.x >> 7;
    int cb    = blockIdx.x & 127;
    int j0    = cb * 16;
    int t = threadIdx.x;
    int w = t >> 5, l = t & 31;

    const float* aptr = g_a + batch * PP;
    float acc[16];
#pragma unroll
    for (int c = 0; c < 16; c++) acc[c] = 0.f;

#pragma unroll
    for (int q = 0; q < 8; q++) {
        int r = t + q * 256;
        const __half* p = g_K + ((size_t)(batch * PP + r)) * PP + j0;
        uint4 k0 = *(const uint4*)p;
        uint4 k1 = *(const uint4*)(p + 8);
        float av = aptr[r];
        const __half2* h0 = (const __half2*)&k0;
        const __half2* h1 = (const __half2*)&k1;
#pragma unroll
        for (int c = 0; c < 4; c++) {
            float2 f = __half22float2(h0[c]);
            acc[2 * c + 0] = fmaf(f.x, av, acc[2 * c + 0]);
            acc[2 * c + 1] = fmaf(f.y, av, acc[2 * c + 1]);
        }
#pragma unroll
        for (int c = 0; c < 4; c++) {
            float2 f = __half22float2(h1[c]);
            acc[8 + 2 * c + 0] = fmaf(f.x, av, acc[8 + 2 * c + 0]);
            acc[8 + 2 * c + 1] = fmaf(f.y, av, acc[8 + 2 * c + 1]);
        }
    }

    __shared__ float sm[8][16];
#pragma unroll
    for (int c = 0; c < 16; c++) {
        float v = acc[c];
#pragma unroll
        for (int off = 16; off; off >>= 1) v += __shfl_xor_sync(0xffffffffu, v, off);
        if (l == c) sm[w][c] = v;   // lane c holds the (identical) reduced value
    }
    __syncthreads();
    if (t < 16) {
        float tj = 0.f;
#pragma unroll
        for (int ww = 0; ww < 8; ww++) tj += sm[ww][t];
        int j = batch * PP + j0 + t;
        g_b[j] = (nu[j] + LOGEPS) / tj;
    }
}

// ---------------------------------------------------------------------------
// Epilogue: pi = a_i * b_j * exp(-C/eps) from exact f32 C; copy C; cost partials.
// grid = 8*512 = 4096 CTAs, 4 rows/CTA, 8 float4 per thread.
// ---------------------------------------------------------------------------
__global__ void __launch_bounds__(256) epilogue_kernel(const float* __restrict__ C,
                                                       float* __restrict__ pi_out,
                                                       float* __restrict__ c_out) {
    int batch = blockIdx.x >> 9;
    int rb    = blockIdx.x & 511;
    int r0    = rb * 4;
    int t = threadIdx.x;
    int w = t >> 5, l = t & 31;

    const float* arow = g_a + batch * PP + r0;
    const float* bptr = g_b + batch * PP;
    float cost = 0.f;
#pragma unroll
    for (int q = 0; q < 8; q++) {
        int f  = t + q * 256;          // float4 index within the 4-row block
        int rl = f >> 9;               // local row 0..3
        int c4 = f & 511;              // float4 column index
        size_t idx = ((size_t)(batch * PP + r0 + rl)) * PP + (size_t)c4 * 4;
        float4 cv = *(const float4*)(C + idx);
        float  a  = arow[rl];
        float4 bv = *(const float4*)(bptr + c4 * 4);
        float4 pv;
        pv.x = a * bv.x * __expf(-INV_EPS * cv.x);
        pv.y = a * bv.y * __expf(-INV_EPS * cv.y);
        pv.z = a * bv.z * __expf(-INV_EPS * cv.z);
        pv.w = a * bv.w * __expf(-INV_EPS * cv.w);
        if (pi_out) *(float4*)(pi_out + idx) = pv;
        if (c_out)  *(float4*)(c_out + idx)  = cv;
        cost += pv.x * cv.x + pv.y * cv.y + pv.z * cv.z + pv.w * cv.w;
    }
#pragma unroll
    for (int off = 16; off; off >>= 1) cost += __shfl_xor_sync(0xffffffffu, cost, off);
    __shared__ float sm[8];
    if (l == 0) sm[w] = cost;
    __syncthreads();
    if (t == 0) {
        float s = 0.f;
#pragma unroll
        for (int i = 0; i < 8; i++) s += sm[i];
        g_part[blockIdx.x] = s;
    }
}

// Final fixed-order cost reduction (deterministic, no float atomics).
__global__ void cost_final_kernel(float* __restrict__ cost_out) {
    int w = threadIdx.x >> 5, l = threadIdx.x & 31;   // warp w = batch w (256 thr = 8 warps)
    float s = 0.f;
#pragma unroll
    for (int m = 0; m < 16; m++) s += g_part[w * 512 + l + m * 32];
#pragma unroll
    for (int off = 16; off; off >>= 1) s += __shfl_xor_sync(0xffffffffu, s, off);
    if (l == 0) cost_out[w] = s;
}

// ---------------------------------------------------------------------------
extern "C" void kernel_launch(void* const* d_in, const int* in_sizes, int n_in,
                              void* d_out, int out_size) {
    const float* C  = (const float*)d_in[0];
    const float* mu = (const float*)d_in[1];
    const float* nu = (const float*)d_in[2];
    float* out = (float*)d_out;

    const long long M  = (long long)M_ELEMS;
    const long long os = (long long)out_size;
    float *cost = nullptr, *pi = nullptr, *cc = nullptr;
    if (os >= 8 + 2 * M)      { cost = out; pi = out + 8; cc = out + 8 + M; }
    else if (os == 2 * M)     { pi = out; cc = out + M; }
    else if (os == M + 8)     { cost = out; pi = out + 8; }
    else if (os == M)         { pi = out; }
    else if (os == 8)         { cost = out; }
    else                      { cost = out; if (os > 8 + M) { pi = out + 8; cc = out + 8 + M; }
                                else if (os > 8) pi = out + 8; }

    prologue_kernel<<<16384, 256>>>(C);
    for (int k = 0; k < NITER; k++) {
        rowpass_kernel<<<256, 128>>>(mu);
        colpass_kernel<<<1024, 256>>>(nu);
    }
    epilogue_kernel<<<4096, 256>>>(C, pi, cc);
    if (cost) cost_final_kernel<<<1, 256>>>(cost);
}